// round 3
// baseline (speedup 1.0000x reference)
#include <cuda_runtime.h>
#include <cstdint>
#include <cstddef>

#define T_ 2048
#define H_ 1024
#define F_ 512
#define E_ 32
#define K_ 4
#define NSLOT (T_*K_)
#define SLOTPAD (NSLOT+64)
#define MAXTILES 160

// ---------------- scratch (device globals; no allocation allowed) ----------
__device__ int   g_cnt[E_];
__device__ int   g_off[E_+1];
__device__ int   g_sel[T_*K_];
__device__ float g_wgt[T_*K_];
__device__ int   g_slotTok[SLOTPAD];     // zero-init pad rows stay 0 forever
__device__ float g_slotW[SLOTPAD];
__device__ int   g_slotOf[T_*K_];
__device__ int   g_tileE[MAXTILES];
__device__ int   g_tileM[MAXTILES];
__device__ float g_Hbuf[(size_t)SLOTPAD*F_];   // ~17 MB
__device__ float g_Ybuf[(size_t)SLOTPAD*H_];   // ~34 MB

// ---------------- helpers ----------------
__device__ __forceinline__ uint32_t f2tf(float x){
    uint32_t r; asm("cvt.rna.tf32.f32 %0, %1;" : "=r"(r) : "f"(x)); return r;
}
__device__ __forceinline__ uint4 tf4(float4 v){
    uint4 r; r.x=f2tf(v.x); r.y=f2tf(v.y); r.z=f2tf(v.z); r.w=f2tf(v.w); return r;
}
__device__ __forceinline__ void mma_tf32(float* c, uint32_t a0,uint32_t a1,uint32_t a2,uint32_t a3,
                                         uint32_t b0,uint32_t b1){
    asm("mma.sync.aligned.m16n8k8.row.col.f32.tf32.tf32.f32 "
        "{%0,%1,%2,%3},{%4,%5,%6,%7},{%8,%9},{%0,%1,%2,%3};"
        : "+f"(c[0]),"+f"(c[1]),"+f"(c[2]),"+f"(c[3])
        : "r"(a0),"r"(a1),"r"(a2),"r"(a3),"r"(b0),"r"(b1));
}

// ---------------- 1. router: exact fp32 logits -----------------------------
__global__ __launch_bounds__(256) void router_kernel(const float* __restrict__ RI,
                                                     const float* __restrict__ WR,
                                                     float* __restrict__ logits){
    if (blockIdx.x==0 && threadIdx.x < E_) g_cnt[threadIdx.x] = 0;
    int t    = (blockIdx.x*256 + threadIdx.x) >> 5;   // warp per token
    int lane = threadIdx.x & 31;
    if (t >= T_) return;
    const float* x = RI + (size_t)t*H_;
    float4 xr[8];
    #pragma unroll
    for (int j=0;j<8;j++) xr[j] = *(const float4*)&x[j*128 + lane*4];
    for (int e=0;e<E_;e++){
        const float* w = WR + (size_t)e*H_;
        float s = 0.f;
        #pragma unroll
        for (int j=0;j<8;j++){
            float4 wv = *(const float4*)&w[j*128 + lane*4];
            s += xr[j].x*wv.x + xr[j].y*wv.y + xr[j].z*wv.z + xr[j].w*wv.w;
        }
        #pragma unroll
        for (int off=16;off;off>>=1) s += __shfl_xor_sync(0xffffffffu, s, off);
        if (lane==0) logits[t*E_ + e] = s;
    }
}

// ---------------- 2. top-4 + softmax + expert counts -----------------------
__global__ __launch_bounds__(256) void topk_kernel(const float* __restrict__ logits){
    int t    = (blockIdx.x*256 + threadIdx.x) >> 5;
    int lane = threadIdx.x & 31;
    if (t >= T_) return;
    float cur = logits[t*E_ + lane];
    int   idx = lane;
    float vsel[K_]; int isel[K_];
    #pragma unroll
    for (int k=0;k<K_;k++){
        float bv = cur; int bi = idx;
        #pragma unroll
        for (int off=16;off;off>>=1){
            float ov = __shfl_xor_sync(0xffffffffu, bv, off);
            int   oi = __shfl_xor_sync(0xffffffffu, bi, off);
            if (ov > bv || (ov == bv && oi < bi)){ bv = ov; bi = oi; }
        }
        vsel[k]=bv; isel[k]=bi;
        if (idx == bi) cur = -__int_as_float(0x7f800000); // -inf
    }
    float mx = vsel[0], den = 0.f, w[K_];
    #pragma unroll
    for (int k=0;k<K_;k++){ w[k] = expf(vsel[k]-mx); den += w[k]; }
    if (lane < K_){
        g_sel[t*K_+lane] = isel[lane];
        g_wgt[t*K_+lane] = w[lane]/den;
        atomicAdd(&g_cnt[isel[lane]], 1);
    }
}

// ---------------- 3. scan + tile table -------------------------------------
__global__ void scan_kernel(){
    if (threadIdx.x != 0) return;
    int acc = 0;
    for (int e=0;e<E_;e++){ g_off[e]=acc; acc += g_cnt[e]; }
    g_off[E_] = acc;
    int tt = 0;
    for (int e=0;e<E_;e++){
        int nt = (g_cnt[e]+63)>>6;
        for (int i=0;i<nt;i++){ g_tileE[tt]=e; g_tileM[tt]=i; tt++; }
    }
    for (; tt<MAXTILES; tt++) g_tileE[tt] = -1;
}

// ---------------- 4. deterministic scatter (block per expert) --------------
__global__ __launch_bounds__(256) void scatter_kernel(){
    int e = blockIdx.x;
    __shared__ int warpSums[8];
    __shared__ int baseSh;
    if (threadIdx.x==0) baseSh = 0;
    __syncthreads();
    int lane = threadIdx.x & 31, wid = threadIdx.x >> 5;
    int off0 = g_off[e];
    for (int t0=0; t0<T_; t0+=256){
        int t = t0 + threadIdx.x;
        int kk = -1;
        #pragma unroll
        for (int k=0;k<K_;k++) if (g_sel[t*K_+k]==e) kk = k;
        int flag = (kk >= 0);
        unsigned m = __ballot_sync(0xffffffffu, flag);
        int wpre = __popc(m & ((1u<<lane)-1u));
        if (lane==0) warpSums[wid] = __popc(m);
        __syncthreads();
        int wbase = 0;
        for (int wj=0; wj<wid; wj++) wbase += warpSums[wj];
        if (flag){
            int gslot = off0 + baseSh + wbase + wpre;
            g_slotTok[gslot] = t;
            g_slotW[gslot]   = g_wgt[t*K_+kk];
            g_slotOf[t*K_+kk]= gslot;
        }
        __syncthreads();
        if (threadIdx.x==0){
            int tot=0;
            for (int wj=0; wj<8; wj++) tot += warpSums[wj];
            baseSh += tot;
        }
        __syncthreads();
    }
}

// ---------------- 5. gathered gate+up grouped GEMM (tf32 mma) ---------------
// tile: 64(M slots) x 64(N of F) x 32(K), 8 warps (4M x 2N), warp = 16x32
__global__ __launch_bounds__(256) void gateup_kernel(const float* __restrict__ X,
                                                     const float* __restrict__ WG,
                                                     const float* __restrict__ WU){
    int tile = blockIdx.x;
    int e = g_tileE[tile];
    if (e < 0) return;
    int m0   = g_tileM[tile]*64;
    int n0   = blockIdx.y*64;
    int base = g_off[e];
    int Me   = g_off[e+1] - base;
    const float* wg = WG + (size_t)e*F_*H_;
    const float* wu = WU + (size_t)e*F_*H_;

    __shared__ uint32_t As [64][36];
    __shared__ uint32_t Bgs[64][36];
    __shared__ uint32_t Bus[64][36];

    int tid  = threadIdx.x;
    int vrow = tid >> 3;          // 0..31
    int vcol = (tid & 7) * 4;     // 0..28
    int tok0 = g_slotTok[base + m0 + vrow];
    int tok1 = g_slotTok[base + m0 + vrow + 32];
    const float* a0p = X + (size_t)tok0*H_ + vcol;
    const float* a1p = X + (size_t)tok1*H_ + vcol;
    const float* g0p = wg + (size_t)(n0+vrow)*H_ + vcol;
    const float* g1p = wg + (size_t)(n0+vrow+32)*H_ + vcol;
    const float* u0p = wu + (size_t)(n0+vrow)*H_ + vcol;
    const float* u1p = wu + (size_t)(n0+vrow+32)*H_ + vcol;

    int lane = tid & 31, wid = tid >> 5;
    int wm = wid & 3, wn = wid >> 2;
    int g  = lane >> 2, tg = lane & 3;

    float accG[4][4] = {}; float accU[4][4] = {};
    float4 pa0,pa1,pg0,pg1,pu0,pu1;
    pa0 = *(const float4*)(a0p); pa1 = *(const float4*)(a1p);
    pg0 = *(const float4*)(g0p); pg1 = *(const float4*)(g1p);
    pu0 = *(const float4*)(u0p); pu1 = *(const float4*)(u1p);

    const int NK = H_/32;
    for (int kt=0; kt<NK; kt++){
        __syncthreads();
        *(uint4*)&As [vrow   ][vcol] = tf4(pa0);
        *(uint4*)&As [vrow+32][vcol] = tf4(pa1);
        *(uint4*)&Bgs[vrow   ][vcol] = tf4(pg0);
        *(uint4*)&Bgs[vrow+32][vcol] = tf4(pg1);
        *(uint4*)&Bus[vrow   ][vcol] = tf4(pu0);
        *(uint4*)&Bus[vrow+32][vcol] = tf4(pu1);
        __syncthreads();
        if (kt+1 < NK){
            int k0 = (kt+1)*32;
            pa0 = *(const float4*)(a0p + k0); pa1 = *(const float4*)(a1p + k0);
            pg0 = *(const float4*)(g0p + k0); pg1 = *(const float4*)(g1p + k0);
            pu0 = *(const float4*)(u0p + k0); pu1 = *(const float4*)(u1p + k0);
        }
        #pragma unroll
        for (int ks=0; ks<4; ks++){
            uint32_t a_0 = As[wm*16+g  ][ks*8+tg  ];
            uint32_t a_1 = As[wm*16+g+8][ks*8+tg  ];
            uint32_t a_2 = As[wm*16+g  ][ks*8+tg+4];
            uint32_t a_3 = As[wm*16+g+8][ks*8+tg+4];
            #pragma unroll
            for (int nf=0; nf<4; nf++){
                int nn = wn*32 + nf*8 + g;
                mma_tf32(accG[nf], a_0,a_1,a_2,a_3, Bgs[nn][ks*8+tg], Bgs[nn][ks*8+tg+4]);
                mma_tf32(accU[nf], a_0,a_1,a_2,a_3, Bus[nn][ks*8+tg], Bus[nn][ks*8+tg+4]);
            }
        }
    }
    // epilogue: h = relu(gate)*up
    #pragma unroll
    for (int nf=0; nf<4; nf++){
        int col = n0 + wn*32 + nf*8 + 2*tg;
        int r0g = m0 + wm*16 + g;
        int r1g = r0g + 8;
        if (r0g < Me){
            size_t o = (size_t)(base+r0g)*F_ + col;
            g_Hbuf[o  ] = fmaxf(accG[nf][0],0.f)*accU[nf][0];
            g_Hbuf[o+1] = fmaxf(accG[nf][1],0.f)*accU[nf][1];
        }
        if (r1g < Me){
            size_t o = (size_t)(base+r1g)*F_ + col;
            g_Hbuf[o  ] = fmaxf(accG[nf][2],0.f)*accU[nf][2];
            g_Hbuf[o+1] = fmaxf(accG[nf][3],0.f)*accU[nf][3];
        }
    }
}

// ---------------- 6. down GEMM (contiguous slots, weight-scaled) ------------
__global__ __launch_bounds__(256) void down_kernel(const float* __restrict__ WD){
    int tile = blockIdx.x;
    int e = g_tileE[tile];
    if (e < 0) return;
    int m0   = g_tileM[tile]*64;
    int n0   = blockIdx.y*64;
    int base = g_off[e];
    int Me   = g_off[e+1] - base;
    const float* wd = WD + (size_t)e*H_*F_;

    __shared__ uint32_t As[64][36];
    __shared__ uint32_t Bs[64][36];

    int tid  = threadIdx.x;
    int vrow = tid >> 3;
    int vcol = (tid & 7) * 4;
    const float* a0p = g_Hbuf + (size_t)(base+m0+vrow)*F_ + vcol;
    const float* a1p = g_Hbuf + (size_t)(base+m0+vrow+32)*F_ + vcol;
    const float* b0p = wd + (size_t)(n0+vrow)*F_ + vcol;
    const float* b1p = wd + (size_t)(n0+vrow+32)*F_ + vcol;

    int lane = tid & 31, wid = tid >> 5;
    int wm = wid & 3, wn = wid >> 2;
    int g  = lane >> 2, tg = lane & 3;

    float acc[4][4] = {};
    float4 pa0,pa1,pb0,pb1;
    pa0 = *(const float4*)(a0p); pa1 = *(const float4*)(a1p);
    pb0 = *(const float4*)(b0p); pb1 = *(const float4*)(b1p);

    const int NK = F_/32;
    for (int kt=0; kt<NK; kt++){
        __syncthreads();
        *(uint4*)&As[vrow   ][vcol] = tf4(pa0);
        *(uint4*)&As[vrow+32][vcol] = tf4(pa1);
        *(uint4*)&Bs[vrow   ][vcol] = tf4(pb0);
        *(uint4*)&Bs[vrow+32][vcol] = tf4(pb1);
        __syncthreads();
        if (kt+1 < NK){
            int k0 = (kt+1)*32;
            pa0 = *(const float4*)(a0p + k0); pa1 = *(const float4*)(a1p + k0);
            pb0 = *(const float4*)(b0p + k0); pb1 = *(const float4*)(b1p + k0);
        }
        #pragma unroll
        for (int ks=0; ks<4; ks++){
            uint32_t a_0 = As[wm*16+g  ][ks*8+tg  ];
            uint32_t a_1 = As[wm*16+g+8][ks*8+tg  ];
            uint32_t a_2 = As[wm*16+g  ][ks*8+tg+4];
            uint32_t a_3 = As[wm*16+g+8][ks*8+tg+4];
            #pragma unroll
            for (int nf=0; nf<4; nf++){
                int nn = wn*32 + nf*8 + g;
                mma_tf32(acc[nf], a_0,a_1,a_2,a_3, Bs[nn][ks*8+tg], Bs[nn][ks*8+tg+4]);
            }
        }
    }
    int r0g = m0 + wm*16 + g;
    int r1g = r0g + 8;
    float w0 = (r0g < Me) ? g_slotW[base+r0g] : 0.f;
    float w1 = (r1g < Me) ? g_slotW[base+r1g] : 0.f;
    #pragma unroll
    for (int nf=0; nf<4; nf++){
        int col = n0 + wn*32 + nf*8 + 2*tg;
        if (r0g < Me){
            size_t o = (size_t)(base+r0g)*H_ + col;
            g_Ybuf[o  ] = acc[nf][0]*w0;
            g_Ybuf[o+1] = acc[nf][1]*w0;
        }
        if (r1g < Me){
            size_t o = (size_t)(base+r1g)*H_ + col;
            g_Ybuf[o  ] = acc[nf][2]*w1;
            g_Ybuf[o+1] = acc[nf][3]*w1;
        }
    }
}

// ---------------- 7. deterministic combine ----------------------------------
__global__ __launch_bounds__(256) void combine_kernel(float* __restrict__ out){
    int t = blockIdx.x;
    int h = threadIdx.x * 4;
    float4 acc = make_float4(0.f,0.f,0.f,0.f);
    #pragma unroll
    for (int k=0;k<K_;k++){
        int s = g_slotOf[t*K_+k];
        float4 v = *(const float4*)&g_Ybuf[(size_t)s*H_ + h];
        acc.x += v.x; acc.y += v.y; acc.z += v.z; acc.w += v.w;
    }
    *(float4*)&out[(size_t)t*H_ + h] = acc;
}

// ---------------- launch ----------------------------------------------------
extern "C" void kernel_launch(void* const* d_in, const int* in_sizes, int n_in,
                              void* d_out, int out_size){
    const float* RI = (const float*)d_in[0];
    const float* HS = (const float*)d_in[1];
    const float* WR = (const float*)d_in[2];
    const float* WG = (const float*)d_in[3];
    const float* WU = (const float*)d_in[4];
    const float* WD = (const float*)d_in[5];
    float* out    = (float*)d_out;
    float* logits = out + (size_t)T_*H_;

    router_kernel <<<T_/8, 256>>>(RI, WR, logits);
    topk_kernel   <<<T_/8, 256>>>(logits);
    scan_kernel   <<<1, 32>>>();
    scatter_kernel<<<E_, 256>>>();
    gateup_kernel <<<dim3(MAXTILES, F_/64), 256>>>(HS, WG, WU);
    down_kernel   <<<dim3(MAXTILES, H_/64), 256>>>(WD);
    combine_kernel<<<T_, 256>>>(out);
}

// round 5
// speedup vs baseline: 1.1440x; 1.1440x over previous
#include <cuda_runtime.h>
#include <cstdint>
#include <cstddef>

#define T_ 2048
#define H_ 1024
#define F_ 512
#define E_ 32
#define K_ 4
#define NSLOT (T_*K_)
#define SLOTPAD (NSLOT+128)
#define MAXTILES 96

// gateup: stage = A(128x32f padded 36) + Bg(64x36) + Bu(64x36)
#define GU_A_BYTES   (128*36*4)
#define GU_B_BYTES   (64*36*4)
#define GU_STG       (GU_A_BYTES + 2*GU_B_BYTES)   // 36864
#define GU_SMEM      (2*GU_STG)                    // 73728
// down: stage = A(128x36) + B(64x36)
#define DN_STG       (GU_A_BYTES + GU_B_BYTES)     // 27648
#define DN_SMEM      (2*DN_STG)                    // 55296

// ---------------- scratch ----------------
__device__ int   g_cnt[E_];
__device__ int   g_pos[E_];
__device__ int   g_off[E_+1];
__device__ int   g_sel[NSLOT];
__device__ float g_wgt[NSLOT];
__device__ int   g_slotTok[SLOTPAD];
__device__ float g_slotW[SLOTPAD];
__device__ int   g_slotOf[NSLOT];
__device__ int   g_tileE[MAXTILES];
__device__ int   g_tileM[MAXTILES];
__device__ float g_Hbuf[(size_t)SLOTPAD*F_];
__device__ float g_Ybuf[(size_t)SLOTPAD*H_];

// ---------------- helpers ----------------
__device__ __forceinline__ uint32_t f2tf(float x){
    uint32_t r; asm("cvt.rna.tf32.f32 %0, %1;" : "=r"(r) : "f"(x)); return r;
}
__device__ __forceinline__ uint32_t smem_u32(const void* p){
    uint32_t a; asm("{ .reg .u64 t; cvta.to.shared.u64 t, %1; cvt.u32.u64 %0, t; }" : "=r"(a) : "l"(p));
    return a;
}
__device__ __forceinline__ void cpa16(uint32_t dst, const void* src){
    asm volatile("cp.async.cg.shared.global [%0], [%1], 16;" :: "r"(dst), "l"(src) : "memory");
}
#define CP_COMMIT() asm volatile("cp.async.commit_group;" ::: "memory")
#define CP_WAIT1()  asm volatile("cp.async.wait_group 1;" ::: "memory")

__device__ __forceinline__ void mma_tf32(float* c, uint32_t a0,uint32_t a1,uint32_t a2,uint32_t a3,
                                         uint32_t b0,uint32_t b1){
    asm("mma.sync.aligned.m16n8k8.row.col.f32.tf32.tf32.f32 "
        "{%0,%1,%2,%3},{%4,%5,%6,%7},{%8,%9},{%0,%1,%2,%3};"
        : "+f"(c[0]),"+f"(c[1]),"+f"(c[2]),"+f"(c[3])
        : "r"(a0),"r"(a1),"r"(a2),"r"(a3),"r"(b0),"r"(b1));
}

// ---------------- 1. router (exact fp32, 2 tokens/warp) --------------------
__global__ __launch_bounds__(256) void router_kernel(const float* __restrict__ RI,
                                                     const float* __restrict__ WR,
                                                     float* __restrict__ logits){
    int gid = blockIdx.x*256 + threadIdx.x;
    if (blockIdx.x==0){
        if (threadIdx.x < E_) g_cnt[threadIdx.x] = 0;
        else if (threadIdx.x < 2*E_) g_pos[threadIdx.x-E_] = 0;
    }
    int warp = gid >> 5, lane = gid & 31;
    int t0 = warp*2;
    if (t0 >= T_) return;
    const float* xa = RI + (size_t)t0*H_;
    const float* xb = RI + (size_t)(t0+1)*H_;
    float4 ra[8], rb[8];
    #pragma unroll
    for (int j=0;j<8;j++){ ra[j] = *(const float4*)&xa[j*128 + lane*4];
                           rb[j] = *(const float4*)&xb[j*128 + lane*4]; }
    for (int e=0;e<E_;e++){
        const float* w = WR + (size_t)e*H_;
        float s0=0.f, s1=0.f;
        #pragma unroll
        for (int j=0;j<8;j++){
            float4 wv = *(const float4*)&w[j*128 + lane*4];
            s0 += ra[j].x*wv.x + ra[j].y*wv.y + ra[j].z*wv.z + ra[j].w*wv.w;
            s1 += rb[j].x*wv.x + rb[j].y*wv.y + rb[j].z*wv.z + rb[j].w*wv.w;
        }
        #pragma unroll
        for (int off=16;off;off>>=1){
            s0 += __shfl_xor_sync(0xffffffffu, s0, off);
            s1 += __shfl_xor_sync(0xffffffffu, s1, off);
        }
        if (lane==0){ logits[t0*E_+e] = s0; logits[(t0+1)*E_+e] = s1; }
    }
}

// ---------------- 2. top-4 + softmax + counts -------------------------------
__global__ __launch_bounds__(256) void topk_kernel(const float* __restrict__ logits){
    int t    = (blockIdx.x*256 + threadIdx.x) >> 5;
    int lane = threadIdx.x & 31;
    if (t >= T_) return;
    float cur = logits[t*E_ + lane];
    int   idx = lane;
    float vsel[K_]; int isel[K_];
    #pragma unroll
    for (int k=0;k<K_;k++){
        float bv = cur; int bi = idx;
        #pragma unroll
        for (int off=16;off;off>>=1){
            float ov = __shfl_xor_sync(0xffffffffu, bv, off);
            int   oi = __shfl_xor_sync(0xffffffffu, bi, off);
            if (ov > bv || (ov == bv && oi < bi)){ bv = ov; bi = oi; }
        }
        vsel[k]=bv; isel[k]=bi;
        if (idx == bi) cur = -__int_as_float(0x7f800000);
    }
    float mx = vsel[0], den = 0.f, w[K_];
    #pragma unroll
    for (int k=0;k<K_;k++){ w[k] = expf(vsel[k]-mx); den += w[k]; }
    if (lane < K_){
        g_sel[t*K_+lane] = isel[lane];
        g_wgt[t*K_+lane] = w[lane]/den;
        atomicAdd(&g_cnt[isel[lane]], 1);
    }
}

// ---------------- 3. scan + 128-row tile table ------------------------------
__global__ void scan_kernel(){
    if (threadIdx.x != 0) return;
    int acc = 0;
    for (int e=0;e<E_;e++){ g_off[e]=acc; acc += g_cnt[e]; }
    g_off[E_] = acc;
    int tt = 0;
    for (int e=0;e<E_;e++){
        int nt = (g_cnt[e]+127)>>7;
        for (int i=0;i<nt;i++){ g_tileE[tt]=e; g_tileM[tt]=i; tt++; }
    }
    for (; tt<MAXTILES; tt++) g_tileE[tt] = -1;
}

// ---------------- 4. scatter (slot permutation is value-invariant) ----------
__global__ __launch_bounds__(256) void scatter_kernel(){
    int idx = blockIdx.x*256 + threadIdx.x;
    if (idx >= NSLOT) return;
    int e = g_sel[idx];
    int slot = g_off[e] + atomicAdd(&g_pos[e], 1);
    g_slotTok[slot] = idx >> 2;
    g_slotW[slot]   = g_wgt[idx];
    g_slotOf[idx]   = slot;
}

// ---------------- 5. gate+up GEMM: 128x64 tile, cp.async 2-stage ------------
// 8 warps: wm=wid&3 (32 rows), wn=wid>>2 (32 cols). Computes G and U accum.
__global__ __launch_bounds__(256,2) void gateup_cp(const float* __restrict__ X,
                                                   const float* __restrict__ WG,
                                                   const float* __restrict__ WU){
    extern __shared__ char smem[];
    int tile = blockIdx.y;
    int e = g_tileE[tile];
    if (e < 0) return;
    int n0 = blockIdx.x*64;
    int m0 = g_tileM[tile]*128;
    int base = g_off[e];
    int Me   = g_off[e+1] - base;
    int tid = threadIdx.x, lane = tid&31, wid = tid>>5;
    uint32_t sb = smem_u32(smem);

    // A: 1024 16B chunks, 4/thread. chunk c: row=c>>3, col=(c&7)*4
    const float* srcA[4]; uint32_t dofA[4];
    #pragma unroll
    for (int i=0;i<4;i++){
        int c = tid + i*256, row = c>>3, col = (c&7)*4;
        int tok = g_slotTok[base + m0 + row];
        srcA[i] = X + (size_t)tok*H_ + col;
        dofA[i] = (uint32_t)(row*36 + col)*4;
    }
    // B gate/up: 512 chunks each, 2/thread
    const float* srcG[2]; const float* srcU[2]; uint32_t dofB[2];
    #pragma unroll
    for (int i=0;i<2;i++){
        int c = tid + i*256, row = c>>3, col = (c&7)*4;
        srcG[i] = WG + (size_t)e*F_*H_ + (size_t)(n0+row)*H_ + col;
        srcU[i] = WU + (size_t)e*F_*H_ + (size_t)(n0+row)*H_ + col;
        dofB[i] = (uint32_t)(row*36 + col)*4;
    }

    const int NK = H_/32;
    // prologue: stages 0,1
    #pragma unroll
    for (int kt=0; kt<2; kt++){
        uint32_t s0 = sb + kt*GU_STG;
        #pragma unroll
        for (int i=0;i<4;i++) cpa16(s0 + dofA[i], srcA[i] + kt*32);
        #pragma unroll
        for (int i=0;i<2;i++){
            cpa16(s0 + GU_A_BYTES            + dofB[i], srcG[i] + kt*32);
            cpa16(s0 + GU_A_BYTES + GU_B_BYTES + dofB[i], srcU[i] + kt*32);
        }
        CP_COMMIT();
    }

    int g = lane>>2, tg = lane&3;
    int wm = wid&3, wn = wid>>2;
    float accG[2][4][4] = {}; float accU[2][4][4] = {};

    for (int kt=0; kt<NK; kt++){
        CP_WAIT1();
        __syncthreads();
        int s = kt & 1;
        const float* A0 = (const float*)(smem + s*GU_STG);
        const float* G0 = (const float*)(smem + s*GU_STG + GU_A_BYTES);
        const float* U0 = (const float*)(smem + s*GU_STG + GU_A_BYTES + GU_B_BYTES);
        #pragma unroll
        for (int ks=0; ks<4; ks++){
            int c0 = ks*8+tg, c1 = c0+4;
            uint32_t a[2][4];
            #pragma unroll
            for (int mt=0; mt<2; mt++){
                int r0 = wm*32 + mt*16 + g;
                a[mt][0] = f2tf(A0[r0*36+c0]);
                a[mt][1] = f2tf(A0[(r0+8)*36+c0]);
                a[mt][2] = f2tf(A0[r0*36+c1]);
                a[mt][3] = f2tf(A0[(r0+8)*36+c1]);
            }
            #pragma unroll
            for (int nf=0; nf<4; nf++){
                int nn = wn*32 + nf*8 + g;
                uint32_t bg0 = f2tf(G0[nn*36+c0]), bg1 = f2tf(G0[nn*36+c1]);
                uint32_t bu0 = f2tf(U0[nn*36+c0]), bu1 = f2tf(U0[nn*36+c1]);
                #pragma unroll
                for (int mt=0; mt<2; mt++){
                    mma_tf32(accG[mt][nf], a[mt][0],a[mt][1],a[mt][2],a[mt][3], bg0,bg1);
                    mma_tf32(accU[mt][nf], a[mt][0],a[mt][1],a[mt][2],a[mt][3], bu0,bu1);
                }
            }
        }
        __syncthreads();
        if (kt+2 < NK){
            uint32_t s0 = sb + s*GU_STG;
            int ko = (kt+2)*32;
            #pragma unroll
            for (int i=0;i<4;i++) cpa16(s0 + dofA[i], srcA[i] + ko);
            #pragma unroll
            for (int i=0;i<2;i++){
                cpa16(s0 + GU_A_BYTES              + dofB[i], srcG[i] + ko);
                cpa16(s0 + GU_A_BYTES + GU_B_BYTES + dofB[i], srcU[i] + ko);
            }
        }
        CP_COMMIT();
    }

    // epilogue: h = relu(gate)*up
    #pragma unroll
    for (int mt=0; mt<2; mt++){
        #pragma unroll
        for (int half=0; half<2; half++){
            int r = wm*32 + mt*16 + half*8 + g;
            if (m0 + r < Me){
                size_t ob = (size_t)(base+m0+r)*F_ + n0;
                #pragma unroll
                for (int nf=0; nf<4; nf++){
                    int col = wn*32 + nf*8 + 2*tg;
                    float2 o;
                    o.x = fmaxf(accG[mt][nf][half*2  ],0.f)*accU[mt][nf][half*2  ];
                    o.y = fmaxf(accG[mt][nf][half*2+1],0.f)*accU[mt][nf][half*2+1];
                    *(float2*)&g_Hbuf[ob + col] = o;
                }
            }
        }
    }
}

// ---------------- 6. down GEMM: 128x64 tile, cp.async 2-stage ---------------
__global__ __launch_bounds__(256,2) void down_cp(const float* __restrict__ WD){
    extern __shared__ char smem[];
    int tile = blockIdx.y;
    int e = g_tileE[tile];
    if (e < 0) return;
    int n0 = blockIdx.x*64;
    int m0 = g_tileM[tile]*128;
    int base = g_off[e];
    int Me   = g_off[e+1] - base;
    int tid = threadIdx.x, lane = tid&31, wid = tid>>5;
    uint32_t sb = smem_u32(smem);

    const float* srcA[4]; uint32_t dofA[4];
    #pragma unroll
    for (int i=0;i<4;i++){
        int c = tid + i*256, row = c>>3, col = (c&7)*4;
        srcA[i] = g_Hbuf + (size_t)(base+m0+row)*F_ + col;
        dofA[i] = (uint32_t)(row*36 + col)*4;
    }
    const float* srcB[2]; uint32_t dofB[2];
    #pragma unroll
    for (int i=0;i<2;i++){
        int c = tid + i*256, row = c>>3, col = (c&7)*4;
        srcB[i] = WD + (size_t)e*H_*F_ + (size_t)(n0+row)*F_ + col;
        dofB[i] = (uint32_t)(row*36 + col)*4;
    }

    const int NK = F_/32;
    #pragma unroll
    for (int kt=0; kt<2; kt++){
        uint32_t s0 = sb + kt*DN_STG;
        #pragma unroll
        for (int i=0;i<4;i++) cpa16(s0 + dofA[i], srcA[i] + kt*32);
        #pragma unroll
        for (int i=0;i<2;i++) cpa16(s0 + GU_A_BYTES + dofB[i], srcB[i] + kt*32);
        CP_COMMIT();
    }

    int g = lane>>2, tg = lane&3;
    int wm = wid&3, wn = wid>>2;
    float acc[2][4][4] = {};

    for (int kt=0; kt<NK; kt++){
        CP_WAIT1();
        __syncthreads();
        int s = kt & 1;
        const float* A0 = (const float*)(smem + s*DN_STG);
        const float* B0 = (const float*)(smem + s*DN_STG + GU_A_BYTES);
        #pragma unroll
        for (int ks=0; ks<4; ks++){
            int c0 = ks*8+tg, c1 = c0+4;
            uint32_t a[2][4];
            #pragma unroll
            for (int mt=0; mt<2; mt++){
                int r0 = wm*32 + mt*16 + g;
                a[mt][0] = f2tf(A0[r0*36+c0]);
                a[mt][1] = f2tf(A0[(r0+8)*36+c0]);
                a[mt][2] = f2tf(A0[r0*36+c1]);
                a[mt][3] = f2tf(A0[(r0+8)*36+c1]);
            }
            #pragma unroll
            for (int nf=0; nf<4; nf++){
                int nn = wn*32 + nf*8 + g;
                uint32_t b0 = f2tf(B0[nn*36+c0]), b1 = f2tf(B0[nn*36+c1]);
                #pragma unroll
                for (int mt=0; mt<2; mt++)
                    mma_tf32(acc[mt][nf], a[mt][0],a[mt][1],a[mt][2],a[mt][3], b0,b1);
            }
        }
        __syncthreads();
        if (kt+2 < NK){
            uint32_t s0 = sb + s*DN_STG;
            int ko = (kt+2)*32;
            #pragma unroll
            for (int i=0;i<4;i++) cpa16(s0 + dofA[i], srcA[i] + ko);
            #pragma unroll
            for (int i=0;i<2;i++) cpa16(s0 + GU_A_BYTES + dofB[i], srcB[i] + ko);
        }
        CP_COMMIT();
    }

    #pragma unroll
    for (int mt=0; mt<2; mt++){
        #pragma unroll
        for (int half=0; half<2; half++){
            int r = wm*32 + mt*16 + half*8 + g;
            if (m0 + r < Me){
                float wsc = g_slotW[base+m0+r];
                size_t ob = (size_t)(base+m0+r)*H_ + n0;
                #pragma unroll
                for (int nf=0; nf<4; nf++){
                    int col = wn*32 + nf*8 + 2*tg;
                    float2 o;
                    o.x = acc[mt][nf][half*2  ]*wsc;
                    o.y = acc[mt][nf][half*2+1]*wsc;
                    *(float2*)&g_Ybuf[ob + col] = o;
                }
            }
        }
    }
}

// ---------------- 7. deterministic combine ----------------------------------
__global__ __launch_bounds__(256) void combine_kernel(float* __restrict__ out){
    int t = blockIdx.x;
    int h = threadIdx.x * 4;
    float4 acc = make_float4(0.f,0.f,0.f,0.f);
    #pragma unroll
    for (int k=0;k<K_;k++){
        int s = g_slotOf[t*K_+k];
        float4 v = *(const float4*)&g_Ybuf[(size_t)s*H_ + h];
        acc.x += v.x; acc.y += v.y; acc.z += v.z; acc.w += v.w;
    }
    *(float4*)&out[(size_t)t*H_ + h] = acc;
}

// ---------------- launch ----------------------------------------------------
extern "C" void kernel_launch(void* const* d_in, const int* in_sizes, int n_in,
                              void* d_out, int out_size){
    const float* RI = (const float*)d_in[0];
    const float* HS = (const float*)d_in[1];
    const float* WR = (const float*)d_in[2];
    const float* WG = (const float*)d_in[3];
    const float* WU = (const float*)d_in[4];
    const float* WD = (const float*)d_in[5];
    float* out    = (float*)d_out;
    float* logits = out + (size_t)T_*H_;

    cudaFuncSetAttribute(gateup_cp, cudaFuncAttributeMaxDynamicSharedMemorySize, GU_SMEM);
    cudaFuncSetAttribute(down_cp,   cudaFuncAttributeMaxDynamicSharedMemorySize, DN_SMEM);

    router_kernel <<<T_/16, 256>>>(RI, WR, logits);
    topk_kernel   <<<T_/8, 256>>>(logits);
    scan_kernel   <<<1, 32>>>();
    scatter_kernel<<<NSLOT/256, 256>>>();
    gateup_cp     <<<dim3(F_/64, MAXTILES), 256, GU_SMEM>>>(HS, WG, WU);
    down_cp       <<<dim3(H_/64, MAXTILES), 256, DN_SMEM>>>(WD);
    combine_kernel<<<T_, 256>>>(out);
}